// round 16
// baseline (speedup 1.0000x reference)
#include <cuda_runtime.h>
#include <math.h>

// Problem constants
#define Bn 256
#define Dn 10
#define Mn 32
#define Pn 36
#define In 8
#define On 16

#define THREADS 320            // 10 warps: warp = d, lane = m

// x smem row stride (P*I=288 + 4 pad) -> conflict-free LDS.128
#define XROW 292
#define XS_FLOATS (Mn * XROW)           // 9344
#define WVS_FLOATS (Dn * Mn * In)       // 2560
#define CSROW 37                        // float row stride for rs (pad)
#define CS_FLOATS (Mn * CSROW)          // 1184
#define SMEM_FLOATS (XS_FLOATS + WVS_FLOATS + CS_FLOATS)   // 13088 -> 52352 B

#define WT_TOTAL (Dn * On * 2 * Mn)     // 10240 float4
#define WT_SLICE (WT_TOTAL / Bn)        // 40 float4 per CTA

#define LOG2E 1.4426950408889634f

typedef unsigned long long u64;

// ---- packed f32x2 helpers (sm_103a dual-lane fp32; PTX-only) ----
__device__ __forceinline__ u64 pk2(float lo, float hi) {
    u64 r; asm("mov.b64 %0, {%1, %2};" : "=l"(r) : "f"(lo), "f"(hi)); return r;
}
__device__ __forceinline__ void upk2(u64 v, float& a, float& b) {
    asm("mov.b64 {%0, %1}, %2;" : "=f"(a), "=f"(b) : "l"(v));
}
__device__ __forceinline__ u64 fma2_(u64 a, u64 b, u64 c) {
    u64 d; asm("fma.rn.f32x2 %0, %1, %2, %3;" : "=l"(d) : "l"(a), "l"(b), "l"(c)); return d;
}
__device__ __forceinline__ u64 mul2_(u64 a, u64 b) {
    u64 d; asm("mul.rn.f32x2 %0, %1, %2;" : "=l"(d) : "l"(a), "l"(b)); return d;
}
__device__ __forceinline__ u64 add2_(u64 a, u64 b) {
    u64 d; asm("add.rn.f32x2 %0, %1, %2;" : "=l"(d) : "l"(a), "l"(b)); return d;
}
// bare exp2 (weights pre-scaled by log2e, so no FMUL feeder)
__device__ __forceinline__ float ex2_(float x) {
    float r; asm("ex2.approx.f32 %0, %1;" : "=f"(r) : "f"(x)); return r;
}

// Transposed W: Wt[d][o][ih][m] as float4 -> coalesced LDG.128 over lane m
__device__ float4 Wt_g[WT_TOTAL];
// Monotonic arrival counter (zero-initialized at module load; epochs of 256
// arrivals per launch -> no reset needed across graph replays).
__device__ u64 arrive_ctr;

// Distributed compute_v: per-lane partials (packed FMA), decimated lane
// reduction, squash. xc is 4 packed pairs. Returns s[o]*k on lanes 2o,2o+1.
__device__ __forceinline__ float compute_v_dist(int d, int m, const u64 xc[4]) {
    const ulonglong2* Wt = (const ulonglong2*)(Wt_g + (d * On * 2) * Mn + m);
    float v[On];
#pragma unroll
    for (int o = 0; o < On; o++) {
        ulonglong2 Wa = __ldg(Wt + (size_t)(2 * o) * Mn);
        ulonglong2 Wb = __ldg(Wt + (size_t)(2 * o + 1) * Mn);
        u64 t = mul2_(Wa.x, xc[0]);
        t = fma2_(Wa.y, xc[1], t);
        t = fma2_(Wb.x, xc[2], t);
        t = fma2_(Wb.y, xc[3], t);
        float tl, th; upk2(t, tl, th);
        v[o] = tl + th;
    }
    bool h = (m & 16);
    float a8[8];
#pragma unroll
    for (int j = 0; j < 8; j++) {
        float send = h ? v[j] : v[j + 8];
        float keep = h ? v[j + 8] : v[j];
        a8[j] = keep + __shfl_xor_sync(0xffffffffu, send, 16);
    }
    h = (m & 8);
    float a4[4];
#pragma unroll
    for (int j = 0; j < 4; j++) {
        float send = h ? a8[j] : a8[j + 4];
        float keep = h ? a8[j + 4] : a8[j];
        a4[j] = keep + __shfl_xor_sync(0xffffffffu, send, 8);
    }
    h = (m & 4);
    float a2[2];
#pragma unroll
    for (int j = 0; j < 2; j++) {
        float send = h ? a4[j] : a4[j + 2];
        float keep = h ? a4[j + 2] : a4[j];
        a2[j] = keep + __shfl_xor_sync(0xffffffffu, send, 4);
    }
    h = (m & 2);
    float send = h ? a2[0] : a2[1];
    float keep = h ? a2[1] : a2[0];
    float s1 = keep + __shfl_xor_sync(0xffffffffu, send, 2);
    s1 += __shfl_xor_sync(0xffffffffu, s1, 1);

    float sq = s1 * s1;
    sq += __shfl_xor_sync(0xffffffffu, sq, 2);
    sq += __shfl_xor_sync(0xffffffffu, sq, 4);
    sq += __shfl_xor_sync(0xffffffffu, sq, 8);
    sq += __shfl_xor_sync(0xffffffffu, sq, 16);
    // fast squash: MUFU.RCP-based divide + MUFU.RSQ (tolerance 1e-3; err ~1e-7)
    float k = __fdividef(sq, 1.0f + sq) * rsqrtf(sq + 1e-7f);
    return s1 * k;
}

__device__ __forceinline__ void bcast_v(float vd, float vo[On]) {
#pragma unroll
    for (int o = 0; o < On; o++)
        vo[o] = __shfl_sync(0xffffffffu, vd, 2 * o);
}

// wv (4 packed pairs) = sum_o W[d,m,o,:] * v[o]  — packed vertical FMA
__device__ __forceinline__ void compute_wv(int d, int m, const float vo[On], u64 wv[4]) {
    const ulonglong2* Wt = (const ulonglong2*)(Wt_g + (d * On * 2) * Mn + m);
    wv[0] = 0ull; wv[1] = 0ull; wv[2] = 0ull; wv[3] = 0ull;
#pragma unroll
    for (int o = 0; o < On; o++) {
        ulonglong2 Wa = __ldg(Wt + (size_t)(2 * o) * Mn);
        ulonglong2 Wb = __ldg(Wt + (size_t)(2 * o + 1) * Mn);
        u64 vv = pk2(vo[o], vo[o]);
        wv[0] = fma2_(Wa.x, vv, wv[0]);
        wv[1] = fma2_(Wa.y, vv, wv[1]);
        wv[2] = fma2_(Wb.x, vv, wv[2]);
        wv[3] = fma2_(Wb.y, vv, wv[3]);
    }
}

// packed dot of x pair-quad with packed weight pairs -> scalar
__device__ __forceinline__ float dot8p(const ulonglong2 xa, const ulonglong2 xq,
                                       const u64 w[4]) {
    u64 t = mul2_(xa.x, w[0]);
    t = fma2_(xa.y, w[1], t);
    t = fma2_(xq.x, w[2], t);
    t = fma2_(xq.y, w[3], t);
    float tl, th; upk2(t, tl, th);
    return tl + th;
}

__global__ __launch_bounds__(THREADS, 2)
void caps_routing_kernel(const float* __restrict__ x,
                         const float* __restrict__ W,
                         float* __restrict__ out) {
    extern __shared__ float sm[];
    float*  xs   = sm;                          // [Mn][XROW]
    float*  wvs  = xs + XS_FLOATS;              // [Dn*Mn][8]
    float*  cs   = wvs + WVS_FLOATS;            // [Mn][CSROW] (rs only)
    float*  xsum = cs;                          // early overlap: [Mn][10]

    const int bidx = blockIdx.x;
    const int tid  = threadIdx.x;
    const int d    = tid >> 5;
    const int m    = tid & 31;

    // ---- WARP 8 specialization: transpose this CTA's Wt slice and announce,
    //      with NO CTA-wide barrier in front of the announce. Other warps go
    //      straight to the x-load (overlapped with the transpose). ----
    u64 spin_target = 0ull;
    if (d == 8) {
        const float4* Wsrc = (const float4*)W;
        {
            int idx = bidx * WT_SLICE + m;
            int mm = idx & 31;
            int r  = idx >> 5;
            int ih = r & 1;  r >>= 1;
            int o  = r & 15;
            int dd = r >> 4;
            Wt_g[idx] = Wsrc[((dd * Mn + mm) * On + o) * 2 + ih];
        }
        if (m < WT_SLICE - 32) {
            int idx = bidx * WT_SLICE + 32 + m;
            int mm = idx & 31;
            int r  = idx >> 5;
            int ih = r & 1;  r >>= 1;
            int o  = r & 15;
            int dd = r >> 4;
            Wt_g[idx] = Wsrc[((dd * Mn + mm) * On + o) * 2 + ih];
        }
        __syncwarp();
        if (m == 0) {
            __threadfence();        // release: slice visible before arrival
            u64 old = atomicAdd(&arrive_ctr, 1ull);
            spin_target = (old / (u64)Bn + 1ull) * (u64)Bn;
        }
    }

    // ---- load x[bidx] into padded smem (coalesced float4; warp 8 joins
    //      after its transpose, overlapped with the other 9 warps) ----
    {
        const float4* xg = (const float4*)(x + (size_t)bidx * (Mn * Pn * In));
        const int row4 = (Pn * In) / 4;   // 72
        for (int idx = tid; idx < Mn * row4; idx += THREADS) {
            int mm = idx / row4;
            int j  = idx - mm * row4;
            ((float4*)(xs + mm * XROW))[j] = xg[idx];
        }
    }
    __syncthreads();

    // ---- cooperative xsum[m][i] = (1/D) * sum_p x[m,p,i] (stride 10, 8B-aligned) ----
    if (tid < Mn * In) {
        int mm = tid >> 3, ii = tid & 7;
        const float* xr = xs + mm * XROW + ii;
        float s = 0.f;
#pragma unroll
        for (int p = 0; p < Pn; p++) s += xr[8 * p];
        xsum[mm * 10 + ii] = s * (1.0f / Dn);
    }

    // ---- wait for all CTAs' Wt slices (entire grid is wave-1 co-resident:
    //      launch_bounds(320,2) -> 296 slots >= 256 CTAs, so no deadlock;
    //      waiter = announcer = warp-8 lane 0, who holds spin_target) ----
    if (d == 8 && m == 0) {
        while (*(volatile u64*)&arrive_ctr < spin_target) { }
        __threadfence();        // acquire: order Wt reads after the wait
    }
    __syncthreads();

    const ulonglong2* xm = (const ulonglong2*)(xs + m * XROW);

    u64 xc[4], wv1[4], wv2[4];
    float vo[On];
    const u64 l2e2 = pk2(LOG2E, LOG2E);

    // ================= iteration 1: c = 1/D =================
#pragma unroll
    for (int j = 0; j < 4; j++)
        xc[j] = *(const u64*)(xsum + m * 10 + 2 * j);

    float vd = compute_v_dist(d, m, xc);
    bcast_v(vd, vo);
    compute_wv(d, m, vo, wv1);
    // pre-scale by log2e: all b-dots land in the exp2 domain (softmax invariant)
#pragma unroll
    for (int j = 0; j < 4; j++) wv1[j] = mul2_(wv1[j], l2e2);

    // publish scaled wv1 for cross-d softmax stats
    {
        u64* w8 = (u64*)(wvs + (d * Mn + m) * In);
        w8[0] = wv1[0]; w8[1] = wv1[1]; w8[2] = wv1[2]; w8[3] = wv1[3];
    }
    __syncthreads();

    // ===== axis-1 (d) softmax stats per (m,p): b'[d] = x_p . wv1'[d,m] =====
    // |b| tightly bounded (squash => ||v||<1, W ~ 0.01) => exp2 safe without
    // max subtraction; store only rs = 1/sum_d exp2(b').
    for (int col = tid; col < Mn * Pn; col += THREADS) {
        int cm = col / Pn, cp = col - cm * Pn;
        ulonglong2 xa = *(const ulonglong2*)(xs + cm * XROW + 8 * cp);
        ulonglong2 xq = *(const ulonglong2*)(xs + cm * XROW + 8 * cp + 4);
        float ssum = 0.f;
#pragma unroll
        for (int dd = 0; dd < Dn; dd++) {
            const u64* w8 = (const u64*)(wvs + (dd * Mn + cm) * In);
            u64 t = mul2_(xa.x, w8[0]);
            t = fma2_(xa.y, w8[1], t);
            t = fma2_(xq.x, w8[2], t);
            t = fma2_(xq.y, w8[3], t);
            float tl, th; upk2(t, tl, th);
            ssum += ex2_(tl + th);
        }
        cs[cm * CSROW + cp] = __fdividef(1.0f, ssum);
    }
    __syncthreads();

    // ================= iteration 2 (b' recomputed on the fly) =================
    {
        const float* rsr = cs + m * CSROW;
        u64 acc[4] = {0ull, 0ull, 0ull, 0ull};
        for (int p = 0; p < Pn; p++) {
            ulonglong2 xa = xm[2 * p], xq = xm[2 * p + 1];
            float c = ex2_(dot8p(xa, xq, wv1)) * rsr[p];
            u64 cc = pk2(c, c);
            acc[0] = fma2_(xa.x, cc, acc[0]);
            acc[1] = fma2_(xa.y, cc, acc[1]);
            acc[2] = fma2_(xq.x, cc, acc[2]);
            acc[3] = fma2_(xq.y, cc, acc[3]);
        }
        xc[0] = acc[0]; xc[1] = acc[1]; xc[2] = acc[2]; xc[3] = acc[3];
    }
    vd = compute_v_dist(d, m, xc);
    bcast_v(vd, vo);
    compute_wv(d, m, vo, wv2);
#pragma unroll
    for (int j = 0; j < 4; j++) wv2[j] = mul2_(wv2[j], l2e2);

    // b'_final(p) = x_p . (wv1' + wv2')   (both pre-scaled -> sum is scaled)
    u64 wvt[4];
#pragma unroll
    for (int j = 0; j < 4; j++) wvt[j] = add2_(wv1[j], wv2[j]);

    // ===== FUSED final: axis-3 softmax (exp2, no max) + weighted x acc =====
    {
        float Z = 0.f;
        u64 acc[4] = {0ull, 0ull, 0ull, 0ull};
        for (int p = 0; p < Pn; p++) {
            ulonglong2 xa = xm[2 * p], xq = xm[2 * p + 1];
            float w = ex2_(dot8p(xa, xq, wvt));
            Z += w;
            u64 w2 = pk2(w, w);
            acc[0] = fma2_(xa.x, w2, acc[0]);
            acc[1] = fma2_(xa.y, w2, acc[1]);
            acc[2] = fma2_(xq.x, w2, acc[2]);
            acc[3] = fma2_(xq.y, w2, acc[3]);
        }
        float rz = __fdividef(1.0f, Z);
        u64 rz2 = pk2(rz, rz);
#pragma unroll
        for (int j = 0; j < 4; j++) xc[j] = mul2_(acc[j], rz2);
    }
    vd = compute_v_dist(d, m, xc);

    if (!(m & 1))
        out[((size_t)bidx * Dn + d) * On + (m >> 1)] = vd;
}

extern "C" void kernel_launch(void* const* d_in, const int* in_sizes, int n_in,
                              void* d_out, int out_size) {
    const float* x = (const float*)d_in[0];
    const float* W = (const float*)d_in[1];
    if (n_in >= 2 && in_sizes[0] == Dn * Mn * On * In) {
        x = (const float*)d_in[1];
        W = (const float*)d_in[0];
    }
    float* out = (float*)d_out;

    size_t smem = SMEM_FLOATS * sizeof(float);
    cudaFuncSetAttribute(caps_routing_kernel,
                         cudaFuncAttributeMaxDynamicSharedMemorySize, (int)smem);
    caps_routing_kernel<<<Bn, THREADS, smem>>>(x, W, out);
}

// round 17
// speedup vs baseline: 1.1511x; 1.1511x over previous
#include <cuda_runtime.h>
#include <math.h>

// Problem constants
#define Bn 256
#define Dn 10
#define Mn 32
#define Pn 36
#define In 8
#define On 16

#define THREADS 320            // 10 warps: warp = d, lane = m

// x smem row stride (P*I=288 + 4 pad) -> conflict-free LDS.128
#define XROW 292
#define XS_FLOATS (Mn * XROW)           // 9344
#define WVS_FLOATS (Dn * Mn * In)       // 2560
#define CSROW 37                        // float row stride for rs (pad)
#define CS_FLOATS (Mn * CSROW)          // 1184
#define SMEM_FLOATS (XS_FLOATS + WVS_FLOATS + CS_FLOATS)   // 13088 -> 52352 B

#define WT_TOTAL (Dn * On * 2 * Mn)     // 10240 float4
#define WT_SLICE (WT_TOTAL / Bn)        // 40 float4 per CTA

typedef unsigned long long u64;

// ---- packed f32x2 helpers (sm_103a dual-lane fp32; PTX-only) ----
__device__ __forceinline__ u64 pk2(float lo, float hi) {
    u64 r; asm("mov.b64 %0, {%1, %2};" : "=l"(r) : "f"(lo), "f"(hi)); return r;
}
__device__ __forceinline__ void upk2(u64 v, float& a, float& b) {
    asm("mov.b64 {%0, %1}, %2;" : "=f"(a), "=f"(b) : "l"(v));
}
__device__ __forceinline__ u64 fma2_(u64 a, u64 b, u64 c) {
    u64 d; asm("fma.rn.f32x2 %0, %1, %2, %3;" : "=l"(d) : "l"(a), "l"(b), "l"(c)); return d;
}
__device__ __forceinline__ u64 mul2_(u64 a, u64 b) {
    u64 d; asm("mul.rn.f32x2 %0, %1, %2;" : "=l"(d) : "l"(a), "l"(b)); return d;
}
__device__ __forceinline__ u64 add2_(u64 a, u64 b) {
    u64 d; asm("add.rn.f32x2 %0, %1, %2;" : "=l"(d) : "l"(a), "l"(b)); return d;
}

// Transposed W: Wt[d][o][ih][m] as float4 -> coalesced LDG.128 over lane m
__device__ float4 Wt_g[WT_TOTAL];
// Monotonic arrival counter (zero-initialized at module load; epochs of 256
// arrivals per launch -> no reset needed across graph replays).
__device__ u64 arrive_ctr;

// Distributed compute_v: per-lane partials (packed FMA), decimated lane
// reduction, squash. xc is 4 packed pairs. Returns s[o]*k on lanes 2o,2o+1.
__device__ __forceinline__ float compute_v_dist(int d, int m, const u64 xc[4]) {
    const ulonglong2* Wt = (const ulonglong2*)(Wt_g + (d * On * 2) * Mn + m);
    float v[On];
#pragma unroll
    for (int o = 0; o < On; o++) {
        ulonglong2 Wa = __ldg(Wt + (size_t)(2 * o) * Mn);
        ulonglong2 Wb = __ldg(Wt + (size_t)(2 * o + 1) * Mn);
        u64 t = mul2_(Wa.x, xc[0]);
        t = fma2_(Wa.y, xc[1], t);
        t = fma2_(Wb.x, xc[2], t);
        t = fma2_(Wb.y, xc[3], t);
        float tl, th; upk2(t, tl, th);
        v[o] = tl + th;
    }
    bool h = (m & 16);
    float a8[8];
#pragma unroll
    for (int j = 0; j < 8; j++) {
        float send = h ? v[j] : v[j + 8];
        float keep = h ? v[j + 8] : v[j];
        a8[j] = keep + __shfl_xor_sync(0xffffffffu, send, 16);
    }
    h = (m & 8);
    float a4[4];
#pragma unroll
    for (int j = 0; j < 4; j++) {
        float send = h ? a8[j] : a8[j + 4];
        float keep = h ? a8[j + 4] : a8[j];
        a4[j] = keep + __shfl_xor_sync(0xffffffffu, send, 8);
    }
    h = (m & 4);
    float a2[2];
#pragma unroll
    for (int j = 0; j < 2; j++) {
        float send = h ? a4[j] : a4[j + 2];
        float keep = h ? a4[j + 2] : a4[j];
        a2[j] = keep + __shfl_xor_sync(0xffffffffu, send, 4);
    }
    h = (m & 2);
    float send = h ? a2[0] : a2[1];
    float keep = h ? a2[1] : a2[0];
    float s1 = keep + __shfl_xor_sync(0xffffffffu, send, 2);
    s1 += __shfl_xor_sync(0xffffffffu, s1, 1);

    float sq = s1 * s1;
    sq += __shfl_xor_sync(0xffffffffu, sq, 2);
    sq += __shfl_xor_sync(0xffffffffu, sq, 4);
    sq += __shfl_xor_sync(0xffffffffu, sq, 8);
    sq += __shfl_xor_sync(0xffffffffu, sq, 16);
    float k = sq / ((1.0f + sq) * sqrtf(sq + 1e-7f));
    return s1 * k;
}

__device__ __forceinline__ void bcast_v(float vd, float vo[On]) {
#pragma unroll
    for (int o = 0; o < On; o++)
        vo[o] = __shfl_sync(0xffffffffu, vd, 2 * o);
}

// wv (4 packed pairs) = sum_o W[d,m,o,:] * v[o]  — packed vertical FMA
__device__ __forceinline__ void compute_wv(int d, int m, const float vo[On], u64 wv[4]) {
    const ulonglong2* Wt = (const ulonglong2*)(Wt_g + (d * On * 2) * Mn + m);
    wv[0] = 0ull; wv[1] = 0ull; wv[2] = 0ull; wv[3] = 0ull;
#pragma unroll
    for (int o = 0; o < On; o++) {
        ulonglong2 Wa = __ldg(Wt + (size_t)(2 * o) * Mn);
        ulonglong2 Wb = __ldg(Wt + (size_t)(2 * o + 1) * Mn);
        u64 vv = pk2(vo[o], vo[o]);
        wv[0] = fma2_(Wa.x, vv, wv[0]);
        wv[1] = fma2_(Wa.y, vv, wv[1]);
        wv[2] = fma2_(Wb.x, vv, wv[2]);
        wv[3] = fma2_(Wb.y, vv, wv[3]);
    }
}

// packed dot of x pair-quad with packed weight pairs -> scalar
__device__ __forceinline__ float dot8p(const ulonglong2 xa, const ulonglong2 xq,
                                       const u64 w[4]) {
    u64 t = mul2_(xa.x, w[0]);
    t = fma2_(xa.y, w[1], t);
    t = fma2_(xq.x, w[2], t);
    t = fma2_(xq.y, w[3], t);
    float tl, th; upk2(t, tl, th);
    return tl + th;
}

__global__ __launch_bounds__(THREADS, 2)
void caps_routing_kernel(const float* __restrict__ x,
                         const float* __restrict__ W,
                         float* __restrict__ out) {
    extern __shared__ float sm[];
    float*  xs   = sm;                          // [Mn][XROW]
    float*  wvs  = xs + XS_FLOATS;              // [Dn*Mn][8]
    float*  cs   = wvs + WVS_FLOATS;            // [Mn][CSROW] (rs only)
    float*  xsum = cs;                          // early overlap: [Mn][10]

    const int bidx = blockIdx.x;
    const int tid  = threadIdx.x;
    const int d    = tid >> 5;
    const int m    = tid & 31;

    // ---- WARP 8 specialization: transpose this CTA's Wt slice and announce,
    //      with NO CTA-wide barrier in front of the announce. Other warps go
    //      straight to the x-load (overlapped with the transpose). ----
    u64 spin_target = 0ull;
    if (d == 8) {
        // 40 float4: lanes 0..31 take idx m, lanes 0..7 additionally m+32
        const float4* Wsrc = (const float4*)W;
        {
            int idx = bidx * WT_SLICE + m;
            int mm = idx & 31;
            int r  = idx >> 5;
            int ih = r & 1;  r >>= 1;
            int o  = r & 15;
            int dd = r >> 4;
            Wt_g[idx] = Wsrc[((dd * Mn + mm) * On + o) * 2 + ih];
        }
        if (m < WT_SLICE - 32) {
            int idx = bidx * WT_SLICE + 32 + m;
            int mm = idx & 31;
            int r  = idx >> 5;
            int ih = r & 1;  r >>= 1;
            int o  = r & 15;
            int dd = r >> 4;
            Wt_g[idx] = Wsrc[((dd * Mn + mm) * On + o) * 2 + ih];
        }
        __syncwarp();
        if (m == 0) {
            __threadfence();        // release: slice visible before arrival
            u64 old = atomicAdd(&arrive_ctr, 1ull);
            spin_target = (old / (u64)Bn + 1ull) * (u64)Bn;
        }
    }

    // ---- load x[bidx] into padded smem (coalesced float4; warp 8 joins
    //      after its transpose, overlapped with the other 9 warps) ----
    {
        const float4* xg = (const float4*)(x + (size_t)bidx * (Mn * Pn * In));
        const int row4 = (Pn * In) / 4;   // 72
        for (int idx = tid; idx < Mn * row4; idx += THREADS) {
            int mm = idx / row4;
            int j  = idx - mm * row4;
            ((float4*)(xs + mm * XROW))[j] = xg[idx];
        }
    }
    __syncthreads();

    // ---- cooperative xsum[m][i] = (1/D) * sum_p x[m,p,i] (stride 10, 8B-aligned) ----
    if (tid < Mn * In) {
        int mm = tid >> 3, ii = tid & 7;
        const float* xr = xs + mm * XROW + ii;
        float s = 0.f;
#pragma unroll
        for (int p = 0; p < Pn; p++) s += xr[8 * p];
        xsum[mm * 10 + ii] = s * (1.0f / Dn);
    }

    // ---- wait for all CTAs' Wt slices (entire grid is wave-1 co-resident:
    //      launch_bounds(320,2) -> 296 slots >= 256 CTAs, so no deadlock;
    //      waiter = announcer = warp-8 lane 0, who holds spin_target) ----
    if (d == 8 && m == 0) {
        while (*(volatile u64*)&arrive_ctr < spin_target) { }
        __threadfence();        // acquire: order Wt reads after the wait
    }
    __syncthreads();

    const ulonglong2* xm = (const ulonglong2*)(xs + m * XROW);

    u64 xc[4], wv1[4], wv2[4];
    float vo[On];

    // ================= iteration 1: c = 1/D =================
#pragma unroll
    for (int j = 0; j < 4; j++)
        xc[j] = *(const u64*)(xsum + m * 10 + 2 * j);

    float vd = compute_v_dist(d, m, xc);
    bcast_v(vd, vo);
    compute_wv(d, m, vo, wv1);

    // publish wv1 for cross-d softmax stats
    {
        u64* w8 = (u64*)(wvs + (d * Mn + m) * In);
        w8[0] = wv1[0]; w8[1] = wv1[1]; w8[2] = wv1[2]; w8[3] = wv1[3];
    }
    __syncthreads();

    // ===== axis-1 (d) softmax stats per (m,p): b[d] = x_p . wv1[d,m] =====
    // |b| tightly bounded (squash => ||v||<1, W ~ 0.01) => exp safe without
    // max subtraction; store only rs = 1/sum_d exp(b).
    for (int col = tid; col < Mn * Pn; col += THREADS) {
        int cm = col / Pn, cp = col - cm * Pn;
        ulonglong2 xa = *(const ulonglong2*)(xs + cm * XROW + 8 * cp);
        ulonglong2 xq = *(const ulonglong2*)(xs + cm * XROW + 8 * cp + 4);
        float ssum = 0.f;
#pragma unroll
        for (int dd = 0; dd < Dn; dd++) {
            const u64* w8 = (const u64*)(wvs + (dd * Mn + cm) * In);
            u64 t = mul2_(xa.x, w8[0]);
            t = fma2_(xa.y, w8[1], t);
            t = fma2_(xq.x, w8[2], t);
            t = fma2_(xq.y, w8[3], t);
            float tl, th; upk2(t, tl, th);
            ssum += __expf(tl + th);
        }
        cs[cm * CSROW + cp] = 1.0f / ssum;
    }
    __syncthreads();

    // ================= iteration 2 (b recomputed on the fly) =================
    {
        const float* rsr = cs + m * CSROW;
        u64 acc[4] = {0ull, 0ull, 0ull, 0ull};
        for (int p = 0; p < Pn; p++) {
            ulonglong2 xa = xm[2 * p], xq = xm[2 * p + 1];
            float c = __expf(dot8p(xa, xq, wv1)) * rsr[p];
            u64 cc = pk2(c, c);
            acc[0] = fma2_(xa.x, cc, acc[0]);
            acc[1] = fma2_(xa.y, cc, acc[1]);
            acc[2] = fma2_(xq.x, cc, acc[2]);
            acc[3] = fma2_(xq.y, cc, acc[3]);
        }
        xc[0] = acc[0]; xc[1] = acc[1]; xc[2] = acc[2]; xc[3] = acc[3];
    }
    vd = compute_v_dist(d, m, xc);
    bcast_v(vd, vo);
    compute_wv(d, m, vo, wv2);

    // b_final(p) = x_p . (wv1 + wv2)
    u64 wvt[4];
#pragma unroll
    for (int j = 0; j < 4; j++) wvt[j] = add2_(wv1[j], wv2[j]);

    // ===== FUSED final: axis-3 softmax (no max needed) + weighted x acc =====
    {
        float Z = 0.f;
        u64 acc[4] = {0ull, 0ull, 0ull, 0ull};
        for (int p = 0; p < Pn; p++) {
            ulonglong2 xa = xm[2 * p], xq = xm[2 * p + 1];
            float w = __expf(dot8p(xa, xq, wvt));
            Z += w;
            u64 w2 = pk2(w, w);
            acc[0] = fma2_(xa.x, w2, acc[0]);
            acc[1] = fma2_(xa.y, w2, acc[1]);
            acc[2] = fma2_(xq.x, w2, acc[2]);
            acc[3] = fma2_(xq.y, w2, acc[3]);
        }
        float rz = 1.0f / Z;
        u64 rz2 = pk2(rz, rz);
#pragma unroll
        for (int j = 0; j < 4; j++) xc[j] = mul2_(acc[j], rz2);
    }
    vd = compute_v_dist(d, m, xc);

    if (!(m & 1))
        out[((size_t)bidx * Dn + d) * On + (m >> 1)] = vd;
}

extern "C" void kernel_launch(void* const* d_in, const int* in_sizes, int n_in,
                              void* d_out, int out_size) {
    const float* x = (const float*)d_in[0];
    const float* W = (const float*)d_in[1];
    if (n_in >= 2 && in_sizes[0] == Dn * Mn * On * In) {
        x = (const float*)d_in[1];
        W = (const float*)d_in[0];
    }
    float* out = (float*)d_out;

    size_t smem = SMEM_FLOATS * sizeof(float);
    cudaFuncSetAttribute(caps_routing_kernel,
                         cudaFuncAttributeMaxDynamicSharedMemorySize, (int)smem);
    caps_routing_kernel<<<Bn, THREADS, smem>>>(x, W, out);
}